// round 2
// baseline (speedup 1.0000x reference)
#include <cuda_runtime.h>
#include <math.h>

#define D 64
#define MAX_N 100000
#define MAX_E 1200000

// Scratch (no allocation allowed): h tile, accumulator, degree.
__device__ __align__(256) float g_h[MAX_N * D];
__device__ __align__(256) float g_acc[MAX_N * D];
__device__ int g_deg[MAX_N];

__device__ __forceinline__ float warp_sum(float v) {
    v += __shfl_xor_sync(0xffffffffu, v, 16);
    v += __shfl_xor_sync(0xffffffffu, v, 8);
    v += __shfl_xor_sync(0xffffffffu, v, 4);
    v += __shfl_xor_sync(0xffffffffu, v, 2);
    v += __shfl_xor_sync(0xffffffffu, v, 1);
    return v;
}

// Zero acc (n_acc floats) and deg (n_deg ints).
__global__ void k_zero(int n_acc, int n_deg) {
    int i = blockIdx.x * blockDim.x + threadIdx.x;
    int str = gridDim.x * blockDim.x;
    for (int j = i; j < n_acc; j += str) g_acc[j] = 0.0f;
    for (int j = i; j < n_deg; j += str) g_deg[j] = 0;
}

// In-degree histogram.
__global__ void k_deg(const int* __restrict__ dst, int E) {
    int i = blockIdx.x * blockDim.x + threadIdx.x;
    int str = gridDim.x * blockDim.x;
    for (; i < E; i += str) atomicAdd(&g_deg[dst[i]], 1);
}

// h[row] = (LOGMAP ? logmap0(x) : x) @ W^T + b
// FROM_ACC: x = g_acc[row] * inv_deg(row)   (layer-2 input, exp/log pair fused away)
// else:     x = x_in[row]                   (layer-1 input = emb)
template <bool LOGMAP, bool FROM_ACC>
__global__ void k_transform(const float* __restrict__ x_in,
                            const float* __restrict__ W,
                            const float* __restrict__ b,
                            const float* __restrict__ curv, int N) {
    __shared__ float Wt[D * D];   // Wt[k*D + j] = W[j*D + k]
    __shared__ float bs[D];
    int tid = threadIdx.x;
    for (int idx = tid; idx < D * D; idx += blockDim.x) {
        int j = idx >> 6, k = idx & 63;
        Wt[k * D + j] = W[idx];
    }
    if (tid < D) bs[tid] = b[tid];
    __syncthreads();

    float sqrtc = sqrtf(fabsf(curv[0]));
    int lane = tid & 31;
    int warp = tid >> 5;
    int nwarp = blockDim.x >> 5;

    for (int row = blockIdx.x * nwarp + warp; row < N; row += gridDim.x * nwarp) {
        float x0, x1;
        if (FROM_ACC) {
            int dg = g_deg[row];
            float inv = (dg > 0) ? 1.0f / (float)dg : 0.0f;
            x0 = g_acc[row * D + lane] * inv;
            x1 = g_acc[row * D + lane + 32] * inv;
        } else {
            x0 = x_in[row * D + lane];
            x1 = x_in[row * D + lane + 32];
        }
        float t0 = x0, t1 = x1;
        if (LOGMAP) {
            float nsq = warp_sum(x0 * x0 + x1 * x1);
            float norm = fmaxf(sqrtf(nsq), 1e-15f);
            float arg = fminf(sqrtc * norm, 1.0f - 1e-7f);
            float ath = 0.5f * log1pf(2.0f * arg / (1.0f - arg));  // artanh
            float s = ath / (sqrtc * norm);
            t0 *= s;
            t1 *= s;
        }
        float a0 = bs[lane], a1 = bs[lane + 32];
#pragma unroll
        for (int k = 0; k < 32; k++) {
            float tk = __shfl_sync(0xffffffffu, t0, k);
            a0 += tk * Wt[k * D + lane];
            a1 += tk * Wt[k * D + lane + 32];
        }
#pragma unroll
        for (int k = 0; k < 32; k++) {
            float tk = __shfl_sync(0xffffffffu, t1, k);
            a0 += tk * Wt[(k + 32) * D + lane];
            a1 += tk * Wt[(k + 32) * D + lane + 32];
        }
        g_h[row * D + lane] = a0;
        g_h[row * D + lane + 32] = a1;
    }
}

// acc[dst] += h[src] — 16 lanes per edge, one float4 vector reduction each.
__global__ void k_scatter(const int* __restrict__ src, const int* __restrict__ dst,
                          int E) {
    int t = blockIdx.x * blockDim.x + threadIdx.x;
    int l = t & 15;
    int e = t >> 4;
    int estr = (gridDim.x * blockDim.x) >> 4;
    const float4* h4 = (const float4*)g_h;
    for (; e < E; e += estr) {
        int s = src[e];
        int d = dst[e];
        float4 v = h4[s * (D / 4) + l];
        float* p = &g_acc[d * D + l * 4];
        asm volatile("red.global.add.v4.f32 [%0], {%1,%2,%3,%4};"
                     :: "l"(p), "f"(v.x), "f"(v.y), "f"(v.z), "f"(v.w)
                     : "memory");
    }
}

// out = expmap0(acc * inv_deg)
__global__ void k_final(float* __restrict__ out, const float* __restrict__ curv,
                        int N) {
    float sqrtc = sqrtf(fabsf(curv[0]));
    int lane = threadIdx.x & 31;
    int warp = threadIdx.x >> 5;
    int nwarp = blockDim.x >> 5;
    for (int row = blockIdx.x * nwarp + warp; row < N; row += gridDim.x * nwarp) {
        int dg = g_deg[row];
        float inv = (dg > 0) ? 1.0f / (float)dg : 0.0f;
        float u0 = g_acc[row * D + lane] * inv;
        float u1 = g_acc[row * D + lane + 32] * inv;
        float nsq = warp_sum(u0 * u0 + u1 * u1);
        float norm = fmaxf(sqrtf(nsq), 1e-15f);
        float z = sqrtc * norm;
        float s = tanhf(z) / z;
        out[row * D + lane] = s * u0;
        out[row * D + lane + 32] = s * u1;
    }
}

extern "C" void kernel_launch(void* const* d_in, const int* in_sizes, int n_in,
                              void* d_out, int out_size) {
    const int* src = (const int*)d_in[0];
    const int* dst = (const int*)d_in[1];
    const float* emb = (const float*)d_in[2];
    const float* W1 = (const float*)d_in[3];
    const float* b1 = (const float*)d_in[4];
    const float* W2 = (const float*)d_in[5];
    const float* b2 = (const float*)d_in[6];
    const float* curv = (const float*)d_in[7];

    int E = in_sizes[0];
    int N = in_sizes[2] / D;
    float* out = (float*)d_out;

    int tb = 256;
    int zero_blocks = 1024;
    int deg_blocks = (E + tb - 1) / tb;
    int tr_blocks = (N + 7) / 8;                       // 8 warps/block, warp per row
    long long sc_threads = (long long)E * 16;
    int sc_blocks = (int)((sc_threads + tb - 1) / tb);
    int fin_blocks = (N + 7) / 8;

    // deg = 0, acc = 0
    k_zero<<<zero_blocks, tb>>>(N * D, N);
    // in-degree
    k_deg<<<deg_blocks, tb>>>(dst, E);
    // layer 1: h = logmap0(emb) @ W1^T + b1
    k_transform<true, false><<<tr_blocks, tb>>>(emb, W1, b1, curv, N);
    // acc[dst] += h[src]
    k_scatter<<<sc_blocks, tb>>>(src, dst, E);
    // layer 2: h = (acc * inv_deg) @ W2^T + b2   (expmap∘logmap fused away)
    k_transform<false, true><<<tr_blocks, tb>>>(nullptr, W2, b2, curv, N);
    // acc = 0 (deg preserved)
    k_zero<<<zero_blocks, tb>>>(N * D, 0);
    // acc[dst] += h[src]
    k_scatter<<<sc_blocks, tb>>>(src, dst, E);
    // out = expmap0(acc * inv_deg)
    k_final<<<fin_blocks, tb>>>(out, curv, N);
}

// round 3
// speedup vs baseline: 2.5652x; 2.5652x over previous
#include <cuda_runtime.h>
#include <math.h>

#define D 64
#define MAX_N 100000
#define MAX_E 1200000
#define SCAN_B 512
#define MAX_PART 1024   // ceil(MAX_N/SCAN_B) = 196 <= 1024

// Scratch (no allocation allowed)
__device__ __align__(256) float g_h[MAX_N * D];
__device__ __align__(256) float g_acc[MAX_N * D];
__device__ int g_deg[MAX_N];
__device__ int g_off[MAX_N];
__device__ int g_cur[MAX_N];
__device__ int g_es[MAX_E];
__device__ int g_part[MAX_PART];
__device__ int g_pbase[MAX_PART];

__device__ __forceinline__ float warp_sum(float v) {
    v += __shfl_xor_sync(0xffffffffu, v, 16);
    v += __shfl_xor_sync(0xffffffffu, v, 8);
    v += __shfl_xor_sync(0xffffffffu, v, 4);
    v += __shfl_xor_sync(0xffffffffu, v, 2);
    v += __shfl_xor_sync(0xffffffffu, v, 1);
    return v;
}

// ---- CSR build ----------------------------------------------------------

__global__ void k_init_deg(int N) {
    int i = blockIdx.x * blockDim.x + threadIdx.x;
    if (i < N) g_deg[i] = 0;
}

__global__ void k_deg(const int* __restrict__ dst, int E) {
    int i = blockIdx.x * blockDim.x + threadIdx.x;
    if (i < E) atomicAdd(&g_deg[dst[i]], 1);
}

// block partial sums of deg
__global__ void k_scan_part(int N) {
    __shared__ int sm[SCAN_B];
    int t = threadIdx.x;
    int i = blockIdx.x * SCAN_B + t;
    sm[t] = (i < N) ? g_deg[i] : 0;
    __syncthreads();
    for (int s = SCAN_B / 2; s > 0; s >>= 1) {
        if (t < s) sm[t] += sm[t + s];
        __syncthreads();
    }
    if (t == 0) g_part[blockIdx.x] = sm[0];
}

// single-block exclusive scan of partials (nPart <= MAX_PART)
__global__ void k_scan_top(int nPart) {
    __shared__ int sm[MAX_PART];
    int t = threadIdx.x;
    int x = (t < nPart) ? g_part[t] : 0;
    sm[t] = x;
    __syncthreads();
    for (int off = 1; off < MAX_PART; off <<= 1) {
        int add = (t >= off) ? sm[t - off] : 0;
        __syncthreads();
        sm[t] += add;
        __syncthreads();
    }
    if (t < nPart) g_pbase[t] = sm[t] - x;
}

// intra-block inclusive scan + base -> exclusive offsets & cursors
__global__ void k_scan_off(int N) {
    __shared__ int sm[SCAN_B];
    int t = threadIdx.x;
    int i = blockIdx.x * SCAN_B + t;
    int x = (i < N) ? g_deg[i] : 0;
    sm[t] = x;
    __syncthreads();
    for (int off = 1; off < SCAN_B; off <<= 1) {
        int add = (t >= off) ? sm[t - off] : 0;
        __syncthreads();
        sm[t] += add;
        __syncthreads();
    }
    if (i < N) {
        int o = g_pbase[blockIdx.x] + sm[t] - x;
        g_off[i] = o;
        g_cur[i] = o;
    }
}

__global__ void k_fill(const int* __restrict__ src, const int* __restrict__ dst,
                       int E) {
    int e = blockIdx.x * blockDim.x + threadIdx.x;
    if (e < E) {
        int d = dst[e];
        int p = atomicAdd(&g_cur[d], 1);
        g_es[p] = src[e];
    }
}

// ---- transform: h[row] = (logmap0? x) @ W^T + b, 4 rows per warp --------

template <bool LOGMAP, bool FROM_ACC>
__global__ void k_transform(const float* __restrict__ x_in,
                            const float* __restrict__ W,
                            const float* __restrict__ b,
                            const float* __restrict__ curv, int N) {
    __shared__ float Wt[D * D];   // Wt[k*D + j] = W[j*D + k]
    __shared__ float bs[D];
    int tid = threadIdx.x;
    for (int idx = tid; idx < D * D; idx += blockDim.x) {
        int j = idx >> 6, k = idx & 63;
        Wt[k * D + j] = W[idx];
    }
    if (tid < D) bs[tid] = b[tid];
    __syncthreads();

    float sqrtc = sqrtf(fabsf(curv[0]));
    int lane = tid & 31;
    int warp = tid >> 5;
    int nwarp = blockDim.x >> 5;
    int base = (blockIdx.x * nwarp + warp) * 4;
    if (base >= N) return;

    float t0[4], t1[4];
#pragma unroll
    for (int i = 0; i < 4; i++) {
        int row = base + i;
        float x0 = 0.0f, x1 = 0.0f;
        if (row < N) {
            if (FROM_ACC) {
                int dg = g_deg[row];
                float inv = (dg > 0) ? 1.0f / (float)dg : 0.0f;
                x0 = g_acc[row * D + lane] * inv;
                x1 = g_acc[row * D + lane + 32] * inv;
            } else {
                x0 = x_in[row * D + lane];
                x1 = x_in[row * D + lane + 32];
            }
        }
        if (LOGMAP) {
            float nsq = warp_sum(x0 * x0 + x1 * x1);
            float norm = fmaxf(sqrtf(nsq), 1e-15f);
            float arg = fminf(sqrtc * norm, 1.0f - 1e-7f);
            float ath = 0.5f * log1pf(2.0f * arg / (1.0f - arg));  // artanh
            float s = ath / (sqrtc * norm);
            x0 *= s;
            x1 *= s;
        }
        t0[i] = x0;
        t1[i] = x1;
    }

    float a0[4], a1[4];
#pragma unroll
    for (int i = 0; i < 4; i++) { a0[i] = bs[lane]; a1[i] = bs[lane + 32]; }

#pragma unroll
    for (int k = 0; k < 32; k++) {
        float w0 = Wt[k * D + lane];
        float w1 = Wt[k * D + lane + 32];
#pragma unroll
        for (int i = 0; i < 4; i++) {
            float tk = __shfl_sync(0xffffffffu, t0[i], k);
            a0[i] += tk * w0;
            a1[i] += tk * w1;
        }
    }
#pragma unroll
    for (int k = 0; k < 32; k++) {
        float w0 = Wt[(k + 32) * D + lane];
        float w1 = Wt[(k + 32) * D + lane + 32];
#pragma unroll
        for (int i = 0; i < 4; i++) {
            float tk = __shfl_sync(0xffffffffu, t1[i], k);
            a0[i] += tk * w0;
            a1[i] += tk * w1;
        }
    }

#pragma unroll
    for (int i = 0; i < 4; i++) {
        int row = base + i;
        if (row < N) {
            g_h[row * D + lane] = a0[i];
            g_h[row * D + lane + 32] = a1[i];
        }
    }
}

// ---- gather: acc[row] = sum over CSR edges of h[src], half-warp per row --

__global__ void k_gather(int N) {
    int t = blockIdx.x * blockDim.x + threadIdx.x;
    int row = t >> 4;
    int c = t & 15;
    if (row >= N) return;
    int beg = g_off[row];
    int cnt = g_deg[row];
    const float4* __restrict__ h4 = (const float4*)g_h;
    float4 a0 = make_float4(0.f, 0.f, 0.f, 0.f);
    float4 a1 = make_float4(0.f, 0.f, 0.f, 0.f);
    int e = 0;
    for (; e + 1 < cnt; e += 2) {
        int s0 = g_es[beg + e];
        int s1 = g_es[beg + e + 1];
        float4 v0 = h4[s0 * (D / 4) + c];
        float4 v1 = h4[s1 * (D / 4) + c];
        a0.x += v0.x; a0.y += v0.y; a0.z += v0.z; a0.w += v0.w;
        a1.x += v1.x; a1.y += v1.y; a1.z += v1.z; a1.w += v1.w;
    }
    if (e < cnt) {
        int s = g_es[beg + e];
        float4 v = h4[s * (D / 4) + c];
        a0.x += v.x; a0.y += v.y; a0.z += v.z; a0.w += v.w;
    }
    a0.x += a1.x; a0.y += a1.y; a0.z += a1.z; a0.w += a1.w;
    ((float4*)g_acc)[row * (D / 4) + c] = a0;
}

// ---- out = expmap0(acc * inv_deg) ---------------------------------------

__global__ void k_final(float* __restrict__ out, const float* __restrict__ curv,
                        int N) {
    float sqrtc = sqrtf(fabsf(curv[0]));
    int lane = threadIdx.x & 31;
    int warp = threadIdx.x >> 5;
    int nwarp = blockDim.x >> 5;
    int row = blockIdx.x * nwarp + warp;
    if (row >= N) return;
    int dg = g_deg[row];
    float inv = (dg > 0) ? 1.0f / (float)dg : 0.0f;
    float u0 = g_acc[row * D + lane] * inv;
    float u1 = g_acc[row * D + lane + 32] * inv;
    float nsq = warp_sum(u0 * u0 + u1 * u1);
    float norm = fmaxf(sqrtf(nsq), 1e-15f);
    float z = sqrtc * norm;
    float s = tanhf(z) / z;   // -> 1 as z -> 0
    out[row * D + lane] = s * u0;
    out[row * D + lane + 32] = s * u1;
}

extern "C" void kernel_launch(void* const* d_in, const int* in_sizes, int n_in,
                              void* d_out, int out_size) {
    const int* src = (const int*)d_in[0];
    const int* dst = (const int*)d_in[1];
    const float* emb = (const float*)d_in[2];
    const float* W1 = (const float*)d_in[3];
    const float* b1 = (const float*)d_in[4];
    const float* W2 = (const float*)d_in[5];
    const float* b2 = (const float*)d_in[6];
    const float* curv = (const float*)d_in[7];

    int E = in_sizes[0];
    int N = in_sizes[2] / D;
    float* out = (float*)d_out;

    int tb = 256;
    int nPart = (N + SCAN_B - 1) / SCAN_B;

    // CSR build
    k_init_deg<<<(N + tb - 1) / tb, tb>>>(N);
    k_deg<<<(E + tb - 1) / tb, tb>>>(dst, E);
    k_scan_part<<<nPart, SCAN_B>>>(N);
    k_scan_top<<<1, MAX_PART>>>(nPart);
    k_scan_off<<<nPart, SCAN_B>>>(N);
    k_fill<<<(E + tb - 1) / tb, tb>>>(src, dst, E);

    // transform grid: 8 warps/block, 4 rows/warp = 32 rows/block
    int tr_blocks = (N + 31) / 32;
    // gather grid: half-warp per row
    int ga_blocks = (N * 16 + tb - 1) / tb;
    int fin_blocks = (N + 7) / 8;

    // layer 1
    k_transform<true, false><<<tr_blocks, tb>>>(emb, W1, b1, curv, N);
    k_gather<<<ga_blocks, tb>>>(N);
    // layer 2 (expmap∘logmap fused away)
    k_transform<false, true><<<tr_blocks, tb>>>(nullptr, W2, b2, curv, N);
    k_gather<<<ga_blocks, tb>>>(N);
    k_final<<<fin_blocks, tb>>>(out, curv, N);
}

// round 5
// speedup vs baseline: 2.7115x; 1.0570x over previous
#include <cuda_runtime.h>
#include <math.h>

#define D 64
#define MAX_N 100000
#define MAX_E 1200000

// Scratch (no allocation allowed)
__device__ __align__(256) float g_h[MAX_N * D];
__device__ __align__(256) float g_acc[MAX_N * D];
__device__ int g_deg[MAX_N];
__device__ int g_off[MAX_N];
__device__ int g_cur[MAX_N];
__device__ int g_es[MAX_E];
__device__ int g_total;

__device__ __forceinline__ float warp_sum(float v) {
    v += __shfl_xor_sync(0xffffffffu, v, 16);
    v += __shfl_xor_sync(0xffffffffu, v, 8);
    v += __shfl_xor_sync(0xffffffffu, v, 4);
    v += __shfl_xor_sync(0xffffffffu, v, 2);
    v += __shfl_xor_sync(0xffffffffu, v, 1);
    return v;
}

// ---- CSR build ----------------------------------------------------------

__global__ void k_init_deg(int N) {
    int i = blockIdx.x * blockDim.x + threadIdx.x;
    if (i < N) g_deg[i] = 0;
    if (i == 0) g_total = 0;
}

__global__ void k_deg(const int* __restrict__ dst, int E) {
    int i = blockIdx.x * blockDim.x + threadIdx.x;
    if (i < E) atomicAdd(&g_deg[dst[i]], 1);
}

// Bucket offsets via warp-aggregated atomic bump (bucket ORDER is irrelevant:
// any contiguous region per dst gives the same gather result set).
__global__ void k_off(int N) {
    int i = blockIdx.x * blockDim.x + threadIdx.x;
    int lane = threadIdx.x & 31;
    int d = (i < N) ? g_deg[i] : 0;
    // warp inclusive scan
    int s = d;
#pragma unroll
    for (int o = 1; o < 32; o <<= 1) {
        int v = __shfl_up_sync(0xffffffffu, s, o);
        if (lane >= o) s += v;
    }
    int wtot = __shfl_sync(0xffffffffu, s, 31);
    int base = 0;
    if (lane == 31 && wtot > 0) base = atomicAdd(&g_total, wtot);
    base = __shfl_sync(0xffffffffu, base, 31);
    if (i < N) {
        int o = base + s - d;   // exclusive within warp
        g_off[i] = o;
        g_cur[i] = o;
    }
}

__global__ void k_fill(const int* __restrict__ src, const int* __restrict__ dst,
                       int E) {
    int e = blockIdx.x * blockDim.x + threadIdx.x;
    if (e < E) {
        int d = dst[e];
        int p = atomicAdd(&g_cur[d], 1);
        g_es[p] = src[e];
    }
}

// ---- transform: h[row] = (logmap0? x) @ W^T + b, 4 rows per warp --------

template <bool LOGMAP, bool FROM_ACC>
__global__ void k_transform(const float* __restrict__ x_in,
                            const float* __restrict__ W,
                            const float* __restrict__ b,
                            const float* __restrict__ curv, int N) {
    __shared__ float Wt[D * D];   // Wt[k*D + j] = W[j*D + k]
    __shared__ float bs[D];
    int tid = threadIdx.x;
    for (int idx = tid; idx < D * D; idx += blockDim.x) {
        int j = idx >> 6, k = idx & 63;
        Wt[k * D + j] = W[idx];
    }
    if (tid < D) bs[tid] = b[tid];
    __syncthreads();

    float sqrtc = sqrtf(fabsf(curv[0]));
    int lane = tid & 31;
    int warp = tid >> 5;
    int nwarp = blockDim.x >> 5;
    int base = (blockIdx.x * nwarp + warp) * 4;
    if (base >= N) return;

    float t0[4], t1[4];
#pragma unroll
    for (int i = 0; i < 4; i++) {
        int row = base + i;
        float x0 = 0.0f, x1 = 0.0f;
        if (row < N) {
            if (FROM_ACC) {
                int dg = g_deg[row];
                float inv = (dg > 0) ? 1.0f / (float)dg : 0.0f;
                x0 = g_acc[row * D + lane] * inv;
                x1 = g_acc[row * D + lane + 32] * inv;
            } else {
                x0 = x_in[row * D + lane];
                x1 = x_in[row * D + lane + 32];
            }
        }
        if (LOGMAP) {
            float nsq = warp_sum(x0 * x0 + x1 * x1);
            float norm = fmaxf(sqrtf(nsq), 1e-15f);
            float arg = fminf(sqrtc * norm, 1.0f - 1e-7f);
            float ath = 0.5f * log1pf(2.0f * arg / (1.0f - arg));  // artanh
            float s = ath / (sqrtc * norm);
            x0 *= s;
            x1 *= s;
        }
        t0[i] = x0;
        t1[i] = x1;
    }

    float a0[4], a1[4];
#pragma unroll
    for (int i = 0; i < 4; i++) { a0[i] = bs[lane]; a1[i] = bs[lane + 32]; }

#pragma unroll
    for (int k = 0; k < 32; k++) {
        float w0 = Wt[k * D + lane];
        float w1 = Wt[k * D + lane + 32];
#pragma unroll
        for (int i = 0; i < 4; i++) {
            float tk = __shfl_sync(0xffffffffu, t0[i], k);
            a0[i] += tk * w0;
            a1[i] += tk * w1;
        }
    }
#pragma unroll
    for (int k = 0; k < 32; k++) {
        float w0 = Wt[(k + 32) * D + lane];
        float w1 = Wt[(k + 32) * D + lane + 32];
#pragma unroll
        for (int i = 0; i < 4; i++) {
            float tk = __shfl_sync(0xffffffffu, t1[i], k);
            a0[i] += tk * w0;
            a1[i] += tk * w1;
        }
    }

#pragma unroll
    for (int i = 0; i < 4; i++) {
        int row = base + i;
        if (row < N) {
            g_h[row * D + lane] = a0[i];
            g_h[row * D + lane + 32] = a1[i];
        }
    }
}

// ---- gather: row = sum over CSR edges of h[src], half-warp per row ------
// FINAL: writes expmap0(sum * inv_deg) to out; else writes raw sum to acc.

template <bool FINAL>
__global__ void k_gather(float* __restrict__ out,
                         const float* __restrict__ curv, int N) {
    int t = blockIdx.x * blockDim.x + threadIdx.x;
    int row = t >> 4;
    int c = t & 15;
    if (row >= N) return;
    int beg = g_off[row];
    int cnt = g_deg[row];
    const float4* __restrict__ h4 = (const float4*)g_h;
    float4 a0 = make_float4(0.f, 0.f, 0.f, 0.f);
    float4 a1 = make_float4(0.f, 0.f, 0.f, 0.f);
    int e = 0;
    for (; e + 1 < cnt; e += 2) {
        int s0 = g_es[beg + e];
        int s1 = g_es[beg + e + 1];
        float4 v0 = h4[s0 * (D / 4) + c];
        float4 v1 = h4[s1 * (D / 4) + c];
        a0.x += v0.x; a0.y += v0.y; a0.z += v0.z; a0.w += v0.w;
        a1.x += v1.x; a1.y += v1.y; a1.z += v1.z; a1.w += v1.w;
    }
    if (e < cnt) {
        int s = g_es[beg + e];
        float4 v = h4[s * (D / 4) + c];
        a0.x += v.x; a0.y += v.y; a0.z += v.z; a0.w += v.w;
    }
    a0.x += a1.x; a0.y += a1.y; a0.z += a1.z; a0.w += a1.w;

    if (!FINAL) {
        ((float4*)g_acc)[row * (D / 4) + c] = a0;
    } else {
        float inv = (cnt > 0) ? 1.0f / (float)cnt : 0.0f;
        a0.x *= inv; a0.y *= inv; a0.z *= inv; a0.w *= inv;
        // norm^2 over the 64-dim row spread across the 16-lane group
        float ns = a0.x * a0.x + a0.y * a0.y + a0.z * a0.z + a0.w * a0.w;
        ns += __shfl_xor_sync(0xffffffffu, ns, 8, 16);
        ns += __shfl_xor_sync(0xffffffffu, ns, 4, 16);
        ns += __shfl_xor_sync(0xffffffffu, ns, 2, 16);
        ns += __shfl_xor_sync(0xffffffffu, ns, 1, 16);
        float sqrtc = sqrtf(fabsf(curv[0]));
        float norm = fmaxf(sqrtf(ns), 1e-15f);
        float z = sqrtc * norm;
        float s = tanhf(z) / z;   // -> 1 as z -> 0
        a0.x *= s; a0.y *= s; a0.z *= s; a0.w *= s;
        ((float4*)out)[row * (D / 4) + c] = a0;
    }
}

extern "C" void kernel_launch(void* const* d_in, const int* in_sizes, int n_in,
                              void* d_out, int out_size) {
    const int* src = (const int*)d_in[0];
    const int* dst = (const int*)d_in[1];
    const float* emb = (const float*)d_in[2];
    const float* W1 = (const float*)d_in[3];
    const float* b1 = (const float*)d_in[4];
    const float* W2 = (const float*)d_in[5];
    const float* b2 = (const float*)d_in[6];
    const float* curv = (const float*)d_in[7];

    int E = in_sizes[0];
    int N = in_sizes[2] / D;
    float* out = (float*)d_out;

    int tb = 256;

    // CSR build (4 kernels)
    k_init_deg<<<(N + tb - 1) / tb, tb>>>(N);
    k_deg<<<(E + tb - 1) / tb, tb>>>(dst, E);
    k_off<<<(N + tb - 1) / tb, tb>>>(N);
    k_fill<<<(E + tb - 1) / tb, tb>>>(src, dst, E);

    int tr_blocks = (N + 31) / 32;              // 8 warps/block, 4 rows/warp
    int ga_blocks = (N * 16 + tb - 1) / tb;     // half-warp per row

    // layer 1
    k_transform<true, false><<<tr_blocks, tb>>>(emb, W1, b1, curv, N);
    k_gather<false><<<ga_blocks, tb>>>(nullptr, curv, N);
    // layer 2 (expmap∘logmap fused away) + final expmap fused into gather
    k_transform<false, true><<<tr_blocks, tb>>>(nullptr, W2, b2, curv, N);
    k_gather<true><<<ga_blocks, tb>>>(out, curv, N);
}